// round 6
// baseline (speedup 1.0000x reference)
#include <cuda_runtime.h>
#include <cstddef>
#include <cstdint>

#define B_   2
#define N_   768
#define BN_  1536
#define D_   512
#define E_   64
#define LN_EPS 1e-5f
#define PADR 68            // kC smem row pitch (floats)
#define XP   130           // kB1 x-tile pitch (floats)
#define WPITCH 66          // kB1 weight-tile pitch (floats)
#define JT   8             // kC j-tiles per block

typedef unsigned long long ull;

// ---------------- scratch ----------------
__device__ float g_Tr[BN_ * E_];    // raw rows = x @ Wr^T
__device__ float g_Tc[BN_ * E_];    // raw cols = x @ Wc^T
__device__ float g_Rc[BN_ * E_];    // centered R'
__device__ float g_Cc[BN_ * E_];    // centered C'
__device__ float g_varR[BN_];
__device__ float g_varC[BN_];

// -------- f32x2 helpers --------
__device__ __forceinline__ void ffma2(ull& d, ull a, ull b) {
    asm("fma.rn.f32x2 %0, %1, %2, %0;" : "+l"(d) : "l"(a), "l"(b));
}
__device__ __forceinline__ ull pack2(float x) {
    ull r; unsigned u = __float_as_uint(x);
    asm("mov.b64 %0, {%1, %1};" : "=l"(r) : "r"(u));
    return r;
}

// ---------------- kernel B1: Tr = x@Wr^T, Tc = x@Wc^T (f32x2 GEMM) ----------
// grid 96, block 256. smem: xs[2080] | wrs[8448] | wcs[8448]; P aliases wrs.
extern __shared__ float sm_b[];
__global__ void __launch_bounds__(256) kB1(const float* __restrict__ x,
                                           const float* __restrict__ Wr,
                                           const float* __restrict__ Wc) {
    float* xs  = sm_b;                 // 2080 floats
    float* wrs = sm_b + 2080;          // 8448
    float* wcs = wrs + 8448;           // 8448
    float* P   = sm_b + 2080;          // alias: 16384 <= 16896

    int tid  = threadIdx.x;
    int f2   = tid & 31;
    int w    = tid >> 5;
    int row0 = blockIdx.x * 16;

    ull aR[16], aC[16];
#pragma unroll
    for (int r = 0; r < 16; r++) { aR[r] = 0ULL; aC[r] = 0ULL; }

    for (int c = 0; c < 4; c++) {
        int d0 = c * 128;
        // raw weights, transposed into smem [dd][f] (pitch 66)
        for (int idx = tid; idx < 8192; idx += 256) {
            int f = idx >> 7, dd = idx & 127;
            wrs[dd * WPITCH + f] = Wr[(size_t)f * D_ + d0 + dd];
            wcs[dd * WPITCH + f] = Wc[(size_t)f * D_ + d0 + dd];
        }
        // x tile: 16 rows x 128 dd
        for (int idx = tid; idx < 1024; idx += 256) {
            int r = idx >> 6, dd2 = idx & 63;
            *(float2*)(xs + r * XP + dd2 * 2) =
                *(const float2*)(x + (size_t)(row0 + r) * D_ + d0 + dd2 * 2);
        }
        __syncthreads();

        int wbase = w * 16;
#pragma unroll
        for (int p = 0; p < 8; p++) {
            int dd = wbase + p * 2;
            ull wr0 = *(const ull*)(wrs + dd * WPITCH + 2 * f2);
            ull wr1 = *(const ull*)(wrs + (dd + 1) * WPITCH + 2 * f2);
            ull wc0 = *(const ull*)(wcs + dd * WPITCH + 2 * f2);
            ull wc1 = *(const ull*)(wcs + (dd + 1) * WPITCH + 2 * f2);
#pragma unroll
            for (int r = 0; r < 16; r++) {
                float2 xv = *(const float2*)(xs + r * XP + dd);
                ull x0 = pack2(xv.x);
                ull x1 = pack2(xv.y);
                ffma2(aR[r], x0, wr0);
                ffma2(aR[r], x1, wr1);
                ffma2(aC[r], x0, wc0);
                ffma2(aC[r], x1, wc1);
            }
        }
        __syncthreads();
    }

    // per-warp partials
#pragma unroll
    for (int r = 0; r < 16; r++) {
        *(ull*)(P + ((w * 2 + 0) * 16 + r) * E_ + 2 * f2) = aR[r];
        *(ull*)(P + ((w * 2 + 1) * 16 + r) * E_ + 2 * f2) = aC[r];
    }
    __syncthreads();

    // reduce 8 warp-partials, write raw Tr/Tc
    int row = tid >> 4;
    int fq  = tid & 15;
    float4 R4 = make_float4(0.f, 0.f, 0.f, 0.f);
    float4 C4 = make_float4(0.f, 0.f, 0.f, 0.f);
#pragma unroll
    for (int ww = 0; ww < 8; ww++) {
        float4 pr = *(const float4*)(P + ((ww * 2 + 0) * 16 + row) * E_ + fq * 4);
        float4 pc = *(const float4*)(P + ((ww * 2 + 1) * 16 + row) * E_ + fq * 4);
        R4.x += pr.x; R4.y += pr.y; R4.z += pr.z; R4.w += pr.w;
        C4.x += pc.x; C4.y += pc.y; C4.z += pc.z; C4.w += pc.w;
    }
    int grow = row0 + row;
    *(float4*)(g_Tr + grow * E_ + fq * 4) = R4;
    *(float4*)(g_Tc + grow * E_ + fq * 4) = C4;
}

// ---------------- kernel B2: apply W_edges + center + variance ---------------
// grid 384, block 256. 4 rows/block; T data is L2-hot (just written by kB1).
__global__ void __launch_bounds__(256) kB2(const float* __restrict__ We) {
    __shared__ float wes[64 * 65];      // We transposed: wes[e*65+f]
    __shared__ float ts[2][4][64];      // Tr/Tc rows
    __shared__ float red[8][4];

    int tid  = threadIdx.x;
    int row0 = blockIdx.x * 4;

    for (int idx = tid; idx < 4096; idx += 256) {
        int f = idx >> 6, e = idx & 63;
        wes[e * 65 + f] = We[f * E_ + e];
    }
    for (int idx = tid; idx < 512; idx += 256) {
        int arr = idx >> 8, r = (idx >> 6) & 3, e = idx & 63;
        ts[arr][r][e] = (arr ? g_Tc : g_Tr)[(row0 + r) * E_ + e];
    }
    __syncthreads();

    int f  = tid & 63;
    int rg = tid >> 6;
    float aR = 0.f, aC = 0.f;
#pragma unroll 8
    for (int e = 0; e < E_; e++) {
        float wv = wes[e * 65 + f];
        aR = fmaf(ts[0][rg][e], wv, aR);
        aC = fmaf(ts[1][rg][e], wv, aC);
    }

    float sR = aR, sRR = aR * aR, sC = aC, sCC = aC * aC;
#pragma unroll
    for (int o = 16; o; o >>= 1) {
        sR  += __shfl_xor_sync(0xffffffffu, sR,  o);
        sRR += __shfl_xor_sync(0xffffffffu, sRR, o);
        sC  += __shfl_xor_sync(0xffffffffu, sC,  o);
        sCC += __shfl_xor_sync(0xffffffffu, sCC, o);
    }
    int w = tid >> 5;
    if ((tid & 31) == 0) { red[w][0] = sR; red[w][1] = sRR; red[w][2] = sC; red[w][3] = sCC; }
    __syncthreads();

    int wp = w ^ 1;
    float tR  = red[w][0] + red[wp][0];
    float tRR = red[w][1] + red[wp][1];
    float tC  = red[w][2] + red[wp][2];
    float tCC = red[w][3] + red[wp][3];
    float mR = tR * (1.f / 64.f);
    float mC = tC * (1.f / 64.f);
    int grow = row0 + rg;
    g_Rc[grow * E_ + f] = aR - mR;
    g_Cc[grow * E_ + f] = aC - mC;
    if (f == 0) {
        g_varR[grow] = tRR * (1.f / 64.f) - mR * mR;
        g_varC[grow] = tCC * (1.f / 64.f) - mC * mC;
    }
}

// ---------------- kernel C: single-wave multi-j-tile epilogue ----------------
// grid (48, 2, 6) = 576 blocks (one wave at 4 blocks/SM). Each block: one
// i-tile (16 rows) x 8 consecutive j-tiles. rs/vR/u loaded once.
__global__ void __launch_bounds__(256, 4) kC(const float* __restrict__ gamma,
                                             const float* __restrict__ beta,
                                             float* __restrict__ out) {
    __shared__ float rs[16 * PADR];
    __shared__ float cs[16 * PADR];
    __shared__ float csg[16 * PADR];
    __shared__ float vR[16];
    __shared__ float vC[16];
    __shared__ float inv[256];

    int i0 = blockIdx.x * 16;
    int b  = blockIdx.y;
    int jg = blockIdx.z;                 // j-group: tiles jg*JT .. jg*JT+JT-1
    int tid = threadIdx.x;
    int rowR = b * N_ + i0;

    for (int idx = tid; idx < 16 * E_; idx += 256) {
        int r = idx >> 6, f = idx & 63;
        rs[r * PADR + f] = g_Rc[(rowR + r) * E_ + f];
    }
    if (tid < 16) vR[tid] = g_varR[rowR + tid];
    __syncthreads();

    int f4 = tid & 15;
    int g  = tid >> 4;
    float4 gm = __ldg((const float4*)gamma + f4);
    float4 bt = __ldg((const float4*)beta + f4);
    float4 rr = ((const float4*)(rs + g * PADR))[f4];
    float4 u;                            // u = r' * gamma (fixed for all j)
    u.x = rr.x * gm.x; u.y = rr.y * gm.y; u.z = rr.z * gm.z; u.w = rr.w * gm.w;

    for (int t = 0; t < JT; t++) {
        int j0 = (jg * JT + t) * 16;
        int rowC = b * N_ + j0;

        for (int idx = tid; idx < 16 * E_; idx += 256) {
            int r = idx >> 6, f = idx & 63;
            float cv = g_Cc[(rowC + r) * E_ + f];
            cs[r * PADR + f]  = cv;
            csg[r * PADR + f] = cv * __ldg(gamma + f);
        }
        if (tid < 16) vC[tid] = g_varC[rowC + tid];
        __syncthreads();

        // phase A: one 64-wide dot per thread -> inv std
        {
            int ii = tid >> 4, jj = tid & 15;
            const float4* r4 = (const float4*)(rs + ii * PADR);
            const float4* c4 = (const float4*)(cs + jj * PADR);
            float d = 0.f;
#pragma unroll
            for (int k = 0; k < 16; k++) {
                float4 a = r4[k], c = c4[k];
                d = fmaf(a.x, c.x, d);
                d = fmaf(a.y, c.y, d);
                d = fmaf(a.z, c.z, d);
                d = fmaf(a.w, c.w, d);
            }
            float var = vR[ii] + vC[jj] + d * (2.f / 64.f);
            inv[tid] = rsqrtf(var + LN_EPS);
        }
        __syncthreads();

        // phase B: streaming stores
        const float4* ivp = (const float4*)(inv + g * 16);
        float4 iva = ivp[0], ivb = ivp[1], ivc = ivp[2], ivd = ivp[3];
        float ivs[16] = {iva.x, iva.y, iva.z, iva.w, ivb.x, ivb.y, ivb.z, ivb.w,
                         ivc.x, ivc.y, ivc.z, ivc.w, ivd.x, ivd.y, ivd.z, ivd.w};
        float4* op = (float4*)out + ((size_t)(b * N_ + i0 + g) * N_ + j0) * 16 + f4;

#pragma unroll
        for (int jj = 0; jj < 16; jj++) {
            float4 v = ((const float4*)(csg + jj * PADR))[f4];
            float iv = ivs[jj];
            float4 o;
            o.x = fmaf(u.x + v.x, iv, bt.x);
            o.y = fmaf(u.y + v.y, iv, bt.y);
            o.z = fmaf(u.z + v.z, iv, bt.z);
            o.w = fmaf(u.w + v.w, iv, bt.w);
            __stcs(op + (size_t)jj * 16, o);
        }
        __syncthreads();   // csg/cs consumed before next tile overwrites
    }
}

// ---------------- launch -------------------------------------------------------
#define KB1_SMEM ((2080 + 8448 + 8448) * 4)

extern "C" void kernel_launch(void* const* d_in, const int* in_sizes, int n_in,
                              void* d_out, int out_size) {
    const float* x     = (const float*)d_in[0];  // [2,768,512]
    const float* Wr    = (const float*)d_in[1];  // [64,512]
    const float* Wc    = (const float*)d_in[2];  // [64,512]
    const float* We    = (const float*)d_in[3];  // [64,64]
    const float* gamma = (const float*)d_in[4];  // [64]
    const float* beta  = (const float*)d_in[5];  // [64]
    float* out = (float*)d_out;                  // [2,768,768,64] fp32

    static int smem_set = 0;
    if (!smem_set) {
        cudaFuncSetAttribute(kB1, cudaFuncAttributeMaxDynamicSharedMemorySize, KB1_SMEM);
        smem_set = 1;
    }

    kB1<<<96, 256, KB1_SMEM>>>(x, Wr, Wc);
    kB2<<<BN_ / 4, 256>>>(We);
    kC<<<dim3(N_ / 16, B_, N_ / 16 / JT), 256>>>(gamma, beta, out);
}

// round 7
// speedup vs baseline: 1.0425x; 1.0425x over previous
#include <cuda_runtime.h>
#include <cstddef>
#include <cstdint>

#define B_   2
#define N_   768
#define BN_  1536
#define D_   512
#define E_   64
#define LN_EPS 1e-5f
#define PADR 68            // kC smem row pitch (floats)
#define XP   130           // kB1 x-tile pitch (floats)
#define JT   8             // kC j-tiles per block

typedef unsigned long long ull;

// ---------------- scratch ----------------
__device__ float g_Wrt[D_ * E_];    // Wr transposed: [d][f]
__device__ float g_Wct[D_ * E_];    // Wc transposed: [d][f]
__device__ float g_Tr[BN_ * E_];    // raw rows = x @ Wr^T
__device__ float g_Tc[BN_ * E_];    // raw cols = x @ Wc^T
__device__ float g_Rc[BN_ * E_];    // centered R'
__device__ float g_Cc[BN_ * E_];    // centered C'
__device__ float g_varR[BN_];
__device__ float g_varC[BN_];

// -------- f32x2 helpers --------
__device__ __forceinline__ void ffma2(ull& d, ull a, ull b) {
    asm("fma.rn.f32x2 %0, %1, %2, %0;" : "+l"(d) : "l"(a), "l"(b));
}
__device__ __forceinline__ ull pack2(float x) {
    ull r; unsigned u = __float_as_uint(x);
    asm("mov.b64 %0, {%1, %1};" : "=l"(r) : "r"(u));
    return r;
}

// ---------------- kernel T: transpose Wr, Wc to [d][f] ------------------------
// grid (16, 2, 2), block 256. Classic 32x32 smem tile, both directions coalesced.
__global__ void __launch_bounds__(256) kT(const float* __restrict__ Wr,
                                          const float* __restrict__ Wc) {
    __shared__ float s[32][33];
    const float* src = blockIdx.z ? Wc : Wr;
    float* dst       = blockIdx.z ? g_Wct : g_Wrt;
    int d0 = blockIdx.x * 32, f0 = blockIdx.y * 32;
    int tx = threadIdx.x & 31, ty = threadIdx.x >> 5;   // ty 0..7
#pragma unroll
    for (int k = 0; k < 32; k += 8)
        s[ty + k][tx] = src[(size_t)(f0 + ty + k) * D_ + d0 + tx];
    __syncthreads();
#pragma unroll
    for (int k = 0; k < 32; k += 8)
        dst[(size_t)(d0 + ty + k) * E_ + f0 + tx] = s[tx][ty + k];
}

// ---------------- kernel B1: Tr = x@Wr^T, Tc = x@Wc^T (proven R2 structure) --
// grid 96, block 256. smem: xs[2080] | wrs[8192] | wcs[8192]; P aliases wrs.
extern __shared__ float sm_b[];
__global__ void __launch_bounds__(256) kB1(const float* __restrict__ x) {
    float* xs  = sm_b;                 // 2080 floats
    float* wrs = sm_b + 2080;          // 8192
    float* wcs = wrs + 8192;           // 8192
    float* P   = sm_b + 2080;          // alias: 16384 floats

    int tid  = threadIdx.x;
    int f2   = tid & 31;
    int w    = tid >> 5;
    int row0 = blockIdx.x * 16;

    ull aR[16], aC[16];
#pragma unroll
    for (int r = 0; r < 16; r++) { aR[r] = 0ULL; aC[r] = 0ULL; }

    for (int c = 0; c < 4; c++) {
        int d0 = c * 128;
        // weight chunk: contiguous float4 from transposed [d][f] layout
        for (int idx = tid; idx < 2048; idx += 256) {
            ((float4*)wrs)[idx] = ((const float4*)(g_Wrt + d0 * E_))[idx];
            ((float4*)wcs)[idx] = ((const float4*)(g_Wct + d0 * E_))[idx];
        }
        // x tile: 16 rows x 128 dd
        for (int idx = tid; idx < 1024; idx += 256) {
            int r = idx >> 6, dd2 = idx & 63;
            *(float2*)(xs + r * XP + dd2 * 2) =
                *(const float2*)(x + (size_t)(row0 + r) * D_ + d0 + dd2 * 2);
        }
        __syncthreads();

        int wbase = w * 16;
#pragma unroll
        for (int p = 0; p < 8; p++) {
            int dd = wbase + p * 2;
            ull wr0 = *(const ull*)(wrs + dd * E_ + 2 * f2);
            ull wr1 = *(const ull*)(wrs + (dd + 1) * E_ + 2 * f2);
            ull wc0 = *(const ull*)(wcs + dd * E_ + 2 * f2);
            ull wc1 = *(const ull*)(wcs + (dd + 1) * E_ + 2 * f2);
#pragma unroll
            for (int r = 0; r < 16; r++) {
                float2 xv = *(const float2*)(xs + r * XP + dd);
                ull x0 = pack2(xv.x);
                ull x1 = pack2(xv.y);
                ffma2(aR[r], x0, wr0);
                ffma2(aR[r], x1, wr1);
                ffma2(aC[r], x0, wc0);
                ffma2(aC[r], x1, wc1);
            }
        }
        __syncthreads();
    }

    // per-warp partials
#pragma unroll
    for (int r = 0; r < 16; r++) {
        *(ull*)(P + ((w * 2 + 0) * 16 + r) * E_ + 2 * f2) = aR[r];
        *(ull*)(P + ((w * 2 + 1) * 16 + r) * E_ + 2 * f2) = aC[r];
    }
    __syncthreads();

    // reduce 8 warp-partials, write raw Tr/Tc
    int row = tid >> 4;
    int fq  = tid & 15;
    float4 R4 = make_float4(0.f, 0.f, 0.f, 0.f);
    float4 C4 = make_float4(0.f, 0.f, 0.f, 0.f);
#pragma unroll
    for (int ww = 0; ww < 8; ww++) {
        float4 pr = *(const float4*)(P + ((ww * 2 + 0) * 16 + row) * E_ + fq * 4);
        float4 pc = *(const float4*)(P + ((ww * 2 + 1) * 16 + row) * E_ + fq * 4);
        R4.x += pr.x; R4.y += pr.y; R4.z += pr.z; R4.w += pr.w;
        C4.x += pc.x; C4.y += pc.y; C4.z += pc.z; C4.w += pc.w;
    }
    int grow = row0 + row;
    *(float4*)(g_Tr + grow * E_ + fq * 4) = R4;
    *(float4*)(g_Tc + grow * E_ + fq * 4) = C4;
}

// ---------------- kernel B2: apply W_edges + center + variance ---------------
// grid 384, block 256. 4 rows/block; T data is L2-hot.
__global__ void __launch_bounds__(256) kB2(const float* __restrict__ We) {
    __shared__ float wes[64 * 65];      // We transposed: wes[e*65+f]
    __shared__ float ts[2][4][64];      // Tr/Tc rows
    __shared__ float red[8][4];

    int tid  = threadIdx.x;
    int row0 = blockIdx.x * 4;

    for (int idx = tid; idx < 4096; idx += 256) {
        int f = idx >> 6, e = idx & 63;
        wes[e * 65 + f] = We[f * E_ + e];
    }
    for (int idx = tid; idx < 512; idx += 256) {
        int arr = idx >> 8, r = (idx >> 6) & 3, e = idx & 63;
        ts[arr][r][e] = (arr ? g_Tc : g_Tr)[(row0 + r) * E_ + e];
    }
    __syncthreads();

    int f  = tid & 63;
    int rg = tid >> 6;
    float aR = 0.f, aC = 0.f;
#pragma unroll 8
    for (int e = 0; e < E_; e++) {
        float wv = wes[e * 65 + f];
        aR = fmaf(ts[0][rg][e], wv, aR);
        aC = fmaf(ts[1][rg][e], wv, aC);
    }

    float sR = aR, sRR = aR * aR, sC = aC, sCC = aC * aC;
#pragma unroll
    for (int o = 16; o; o >>= 1) {
        sR  += __shfl_xor_sync(0xffffffffu, sR,  o);
        sRR += __shfl_xor_sync(0xffffffffu, sRR, o);
        sC  += __shfl_xor_sync(0xffffffffu, sC,  o);
        sCC += __shfl_xor_sync(0xffffffffu, sCC, o);
    }
    int w = tid >> 5;
    if ((tid & 31) == 0) { red[w][0] = sR; red[w][1] = sRR; red[w][2] = sC; red[w][3] = sCC; }
    __syncthreads();

    int wp = w ^ 1;
    float tR  = red[w][0] + red[wp][0];
    float tRR = red[w][1] + red[wp][1];
    float tC  = red[w][2] + red[wp][2];
    float tCC = red[w][3] + red[wp][3];
    float mR = tR * (1.f / 64.f);
    float mC = tC * (1.f / 64.f);
    int grow = row0 + rg;
    g_Rc[grow * E_ + f] = aR - mR;
    g_Cc[grow * E_ + f] = aC - mC;
    if (f == 0) {
        g_varR[grow] = tRR * (1.f / 64.f) - mR * mR;
        g_varC[grow] = tCC * (1.f / 64.f) - mC * mC;
    }
}

// ---------------- kernel C: single-wave multi-j-tile epilogue (unchanged) ----
__global__ void __launch_bounds__(256, 4) kC(const float* __restrict__ gamma,
                                             const float* __restrict__ beta,
                                             float* __restrict__ out) {
    __shared__ float rs[16 * PADR];
    __shared__ float cs[16 * PADR];
    __shared__ float csg[16 * PADR];
    __shared__ float vR[16];
    __shared__ float vC[16];
    __shared__ float inv[256];

    int i0 = blockIdx.x * 16;
    int b  = blockIdx.y;
    int jg = blockIdx.z;
    int tid = threadIdx.x;
    int rowR = b * N_ + i0;

    for (int idx = tid; idx < 16 * E_; idx += 256) {
        int r = idx >> 6, f = idx & 63;
        rs[r * PADR + f] = g_Rc[(rowR + r) * E_ + f];
    }
    if (tid < 16) vR[tid] = g_varR[rowR + tid];
    __syncthreads();

    int f4 = tid & 15;
    int g  = tid >> 4;
    float4 gm = __ldg((const float4*)gamma + f4);
    float4 bt = __ldg((const float4*)beta + f4);
    float4 rr = ((const float4*)(rs + g * PADR))[f4];
    float4 u;                            // u = r' * gamma (fixed for all j)
    u.x = rr.x * gm.x; u.y = rr.y * gm.y; u.z = rr.z * gm.z; u.w = rr.w * gm.w;

    for (int t = 0; t < JT; t++) {
        int j0 = (jg * JT + t) * 16;
        int rowC = b * N_ + j0;

        for (int idx = tid; idx < 16 * E_; idx += 256) {
            int r = idx >> 6, f = idx & 63;
            float cv = g_Cc[(rowC + r) * E_ + f];
            cs[r * PADR + f]  = cv;
            csg[r * PADR + f] = cv * __ldg(gamma + f);
        }
        if (tid < 16) vC[tid] = g_varC[rowC + tid];
        __syncthreads();

        // phase A: one 64-wide dot per thread -> inv std
        {
            int ii = tid >> 4, jj = tid & 15;
            const float4* r4 = (const float4*)(rs + ii * PADR);
            const float4* c4 = (const float4*)(cs + jj * PADR);
            float d = 0.f;
#pragma unroll
            for (int k = 0; k < 16; k++) {
                float4 a = r4[k], c = c4[k];
                d = fmaf(a.x, c.x, d);
                d = fmaf(a.y, c.y, d);
                d = fmaf(a.z, c.z, d);
                d = fmaf(a.w, c.w, d);
            }
            float var = vR[ii] + vC[jj] + d * (2.f / 64.f);
            inv[tid] = rsqrtf(var + LN_EPS);
        }
        __syncthreads();

        // phase B: streaming stores
        const float4* ivp = (const float4*)(inv + g * 16);
        float4 iva = ivp[0], ivb = ivp[1], ivc = ivp[2], ivd = ivp[3];
        float ivs[16] = {iva.x, iva.y, iva.z, iva.w, ivb.x, ivb.y, ivb.z, ivb.w,
                         ivc.x, ivc.y, ivc.z, ivc.w, ivd.x, ivd.y, ivd.z, ivd.w};
        float4* op = (float4*)out + ((size_t)(b * N_ + i0 + g) * N_ + j0) * 16 + f4;

#pragma unroll
        for (int jj = 0; jj < 16; jj++) {
            float4 v = ((const float4*)(csg + jj * PADR))[f4];
            float iv = ivs[jj];
            float4 o;
            o.x = fmaf(u.x + v.x, iv, bt.x);
            o.y = fmaf(u.y + v.y, iv, bt.y);
            o.z = fmaf(u.z + v.z, iv, bt.z);
            o.w = fmaf(u.w + v.w, iv, bt.w);
            __stcs(op + (size_t)jj * 16, o);
        }
        __syncthreads();
    }
}

// ---------------- launch -------------------------------------------------------
#define KB1_SMEM ((2080 + 8192 + 8192) * 4)

extern "C" void kernel_launch(void* const* d_in, const int* in_sizes, int n_in,
                              void* d_out, int out_size) {
    const float* x     = (const float*)d_in[0];  // [2,768,512]
    const float* Wr    = (const float*)d_in[1];  // [64,512]
    const float* Wc    = (const float*)d_in[2];  // [64,512]
    const float* We    = (const float*)d_in[3];  // [64,64]
    const float* gamma = (const float*)d_in[4];  // [64]
    const float* beta  = (const float*)d_in[5];  // [64]
    float* out = (float*)d_out;                  // [2,768,768,64] fp32

    static int smem_set = 0;
    if (!smem_set) {
        cudaFuncSetAttribute(kB1, cudaFuncAttributeMaxDynamicSharedMemorySize, KB1_SMEM);
        smem_set = 1;
    }

    kT<<<dim3(16, 2, 2), 256>>>(Wr, Wc);
    kB1<<<96, 256, KB1_SMEM>>>(x);
    kB2<<<BN_ / 4, 256>>>(We);
    kC<<<dim3(N_ / 16, B_, N_ / 16 / JT), 256>>>(gamma, beta, out);
}

// round 8
// speedup vs baseline: 1.0784x; 1.0345x over previous
#include <cuda_runtime.h>
#include <cstddef>
#include <cstdint>

#define B_   2
#define N_   768
#define BN_  1536
#define D_   512
#define E_   64
#define LN_EPS 1e-5f
#define PADR 68            // kC smem row pitch (floats)
#define XP   130           // kB1 x-tile pitch (floats)
#define JT   8             // kC j-tiles per block

typedef unsigned long long ull;

// ---------------- scratch ----------------
__device__ float g_Wrt[D_ * E_];    // Wr transposed: [d][f]
__device__ float g_Wct[D_ * E_];    // Wc transposed: [d][f]
__device__ float g_Tr[BN_ * E_];    // raw rows = x @ Wr^T
__device__ float g_Tc[BN_ * E_];    // raw cols = x @ Wc^T
__device__ float g_Rc[BN_ * E_];    // centered R'
__device__ float g_Cc[BN_ * E_];    // centered C'
__device__ float g_varR[BN_];
__device__ float g_varC[BN_];

// -------- f32x2 helpers --------
__device__ __forceinline__ void ffma2(ull& d, ull a, ull b) {
    asm("fma.rn.f32x2 %0, %1, %2, %0;" : "+l"(d) : "l"(a), "l"(b));
}
__device__ __forceinline__ ull pack2(float x) {
    ull r; unsigned u = __float_as_uint(x);
    asm("mov.b64 %0, {%1, %1};" : "=l"(r) : "r"(u));
    return r;
}

// ---------------- kernel T: transpose Wr, Wc to [d][f] ------------------------
__global__ void __launch_bounds__(256) kT(const float* __restrict__ Wr,
                                          const float* __restrict__ Wc) {
    __shared__ float s[32][33];
    const float* src = blockIdx.z ? Wc : Wr;
    float* dst       = blockIdx.z ? g_Wct : g_Wrt;
    int d0 = blockIdx.x * 32, f0 = blockIdx.y * 32;
    int tx = threadIdx.x & 31, ty = threadIdx.x >> 5;
#pragma unroll
    for (int k = 0; k < 32; k += 8)
        s[ty + k][tx] = src[(size_t)(f0 + ty + k) * D_ + d0 + tx];
    __syncthreads();
#pragma unroll
    for (int k = 0; k < 32; k += 8)
        dst[(size_t)(d0 + ty + k) * E_ + f0 + tx] = s[tx][ty + k];
}

// ---------------- kernel B1: Tr = x@Wr^T, Tc = x@Wc^T ------------------------
// grid 192 (8 rows/block), block 256. smem: xs[1040] | wrs[8192] | wcs[8192].
// P (8 warps x 2 x 8 rows x 64 = 8192 floats) aliases wrs.
extern __shared__ float sm_b[];
__global__ void __launch_bounds__(256) kB1(const float* __restrict__ x) {
    float* xs  = sm_b;                 // 1040 floats (8 rows x pitch 130)
    float* wrs = sm_b + 1040;          // 8192
    float* wcs = wrs + 8192;           // 8192
    float* P   = sm_b + 1040;          // alias: 8192 floats

    int tid  = threadIdx.x;
    int f2   = tid & 31;
    int w    = tid >> 5;
    int row0 = blockIdx.x * 8;

    ull aR[8], aC[8];
#pragma unroll
    for (int r = 0; r < 8; r++) { aR[r] = 0ULL; aC[r] = 0ULL; }

    for (int c = 0; c < 4; c++) {
        int d0 = c * 128;
        for (int idx = tid; idx < 2048; idx += 256) {
            ((float4*)wrs)[idx] = ((const float4*)(g_Wrt + d0 * E_))[idx];
            ((float4*)wcs)[idx] = ((const float4*)(g_Wct + d0 * E_))[idx];
        }
        for (int idx = tid; idx < 512; idx += 256) {
            int r = idx >> 6, dd2 = idx & 63;
            *(float2*)(xs + r * XP + dd2 * 2) =
                *(const float2*)(x + (size_t)(row0 + r) * D_ + d0 + dd2 * 2);
        }
        __syncthreads();

        int wbase = w * 16;
#pragma unroll
        for (int p = 0; p < 8; p++) {
            int dd = wbase + p * 2;
            ull wr0 = *(const ull*)(wrs + dd * E_ + 2 * f2);
            ull wr1 = *(const ull*)(wrs + (dd + 1) * E_ + 2 * f2);
            ull wc0 = *(const ull*)(wcs + dd * E_ + 2 * f2);
            ull wc1 = *(const ull*)(wcs + (dd + 1) * E_ + 2 * f2);
#pragma unroll
            for (int r = 0; r < 8; r++) {
                float2 xv = *(const float2*)(xs + r * XP + dd);
                ull x0 = pack2(xv.x);
                ull x1 = pack2(xv.y);
                ffma2(aR[r], x0, wr0);
                ffma2(aR[r], x1, wr1);
                ffma2(aC[r], x0, wc0);
                ffma2(aC[r], x1, wc1);
            }
        }
        __syncthreads();
    }

#pragma unroll
    for (int r = 0; r < 8; r++) {
        *(ull*)(P + ((w * 2 + 0) * 8 + r) * E_ + 2 * f2) = aR[r];
        *(ull*)(P + ((w * 2 + 1) * 8 + r) * E_ + 2 * f2) = aC[r];
    }
    __syncthreads();

    // final reduce: thread = (row[3b], arr[1b], fq[4b])
    int row = tid >> 5;
    int arr = (tid >> 4) & 1;
    int fq  = tid & 15;
    float4 A = make_float4(0.f, 0.f, 0.f, 0.f);
#pragma unroll
    for (int ww = 0; ww < 8; ww++) {
        float4 p = *(const float4*)(P + ((ww * 2 + arr) * 8 + row) * E_ + fq * 4);
        A.x += p.x; A.y += p.y; A.z += p.z; A.w += p.w;
    }
    int grow = row0 + row;
    float* dst = arr ? g_Tc : g_Tr;
    *(float4*)(dst + grow * E_ + fq * 4) = A;
}

// ---------------- kernel B2: apply W_edges + center + variance ---------------
__global__ void __launch_bounds__(256) kB2(const float* __restrict__ We) {
    __shared__ float wes[64 * 65];
    __shared__ float ts[2][4][64];
    __shared__ float red[8][4];

    int tid  = threadIdx.x;
    int row0 = blockIdx.x * 4;

    for (int idx = tid; idx < 4096; idx += 256) {
        int f = idx >> 6, e = idx & 63;
        wes[e * 65 + f] = We[f * E_ + e];
    }
    for (int idx = tid; idx < 512; idx += 256) {
        int arr = idx >> 8, r = (idx >> 6) & 3, e = idx & 63;
        ts[arr][r][e] = (arr ? g_Tc : g_Tr)[(row0 + r) * E_ + e];
    }
    __syncthreads();

    int f  = tid & 63;
    int rg = tid >> 6;
    float aR = 0.f, aC = 0.f;
#pragma unroll 8
    for (int e = 0; e < E_; e++) {
        float wv = wes[e * 65 + f];
        aR = fmaf(ts[0][rg][e], wv, aR);
        aC = fmaf(ts[1][rg][e], wv, aC);
    }

    float sR = aR, sRR = aR * aR, sC = aC, sCC = aC * aC;
#pragma unroll
    for (int o = 16; o; o >>= 1) {
        sR  += __shfl_xor_sync(0xffffffffu, sR,  o);
        sRR += __shfl_xor_sync(0xffffffffu, sRR, o);
        sC  += __shfl_xor_sync(0xffffffffu, sC,  o);
        sCC += __shfl_xor_sync(0xffffffffu, sCC, o);
    }
    int w = tid >> 5;
    if ((tid & 31) == 0) { red[w][0] = sR; red[w][1] = sRR; red[w][2] = sC; red[w][3] = sCC; }
    __syncthreads();

    int wp = w ^ 1;
    float tR  = red[w][0] + red[wp][0];
    float tRR = red[w][1] + red[wp][1];
    float tC  = red[w][2] + red[wp][2];
    float tCC = red[w][3] + red[wp][3];
    float mR = tR * (1.f / 64.f);
    float mC = tC * (1.f / 64.f);
    int grow = row0 + rg;
    g_Rc[grow * E_ + f] = aR - mR;
    g_Cc[grow * E_ + f] = aC - mC;
    if (f == 0) {
        g_varR[grow] = tRR * (1.f / 64.f) - mR * mR;
        g_varC[grow] = tCC * (1.f / 64.f) - mC * mC;
    }
}

// ---------------- kernel C: pipelined multi-j-tile epilogue ------------------
// grid (48, 2, 6) = 576 blocks. Double-buffered cs, register prefetch,
// gamma folded into store math (no csg), 2 barriers/tile.
__global__ void __launch_bounds__(256, 4) kC(const float* __restrict__ gamma,
                                             const float* __restrict__ beta,
                                             float* __restrict__ out) {
    __shared__ float rs[16 * PADR];
    __shared__ float cs[2][16 * PADR];
    __shared__ float vR[16];
    __shared__ float vC[2][16];
    __shared__ float inv[256];

    int i0 = blockIdx.x * 16;
    int b  = blockIdx.y;
    int jg = blockIdx.z;
    int tid = threadIdx.x;
    int rowR = b * N_ + i0;
    int rw = tid >> 4;           // row index for loads / i-row for stores
    int f4 = tid & 15;

    // rs: one LDG.128 per thread
    ((float4*)(rs + rw * PADR))[f4] = ((const float4*)(g_Rc + (size_t)(rowR + rw) * E_))[f4];
    if (tid < 16) vR[tid] = g_varR[rowR + tid];
    // preload j-tile 0
    {
        int rowC = b * N_ + jg * JT * 16;
        ((float4*)(cs[0] + rw * PADR))[f4] = ((const float4*)(g_Cc + (size_t)(rowC + rw) * E_))[f4];
        if (tid < 16) vC[0][tid] = g_varC[rowC + tid];
    }
    __syncthreads();

    float4 gm = __ldg((const float4*)gamma + f4);
    float4 bt = __ldg((const float4*)beta + f4);
    float4 rr = ((const float4*)(rs + rw * PADR))[f4];
    float4 u;                            // u = r' * gamma
    u.x = rr.x * gm.x; u.y = rr.y * gm.y; u.z = rr.z * gm.z; u.w = rr.w * gm.w;

    for (int t = 0; t < JT; t++) {
        int cur = t & 1, nxt = cur ^ 1;
        float* csc = cs[cur];

        // prefetch next tile into registers (latency overlapped with A+B)
        float4 pc;
        float pv = 0.f;
        if (t + 1 < JT) {
            int rowCn = b * N_ + (jg * JT + t + 1) * 16;
            pc = ((const float4*)(g_Cc + (size_t)(rowCn + rw) * E_))[f4];
            if (tid < 16) pv = g_varC[rowCn + tid];
        }

        // phase A: one 64-wide dot per thread -> inv std
        {
            int ii = tid >> 4, jj = tid & 15;
            const float4* r4 = (const float4*)(rs + ii * PADR);
            const float4* c4 = (const float4*)(csc + jj * PADR);
            float d = 0.f;
#pragma unroll
            for (int k = 0; k < 16; k++) {
                float4 a = r4[k], c = c4[k];
                d = fmaf(a.x, c.x, d);
                d = fmaf(a.y, c.y, d);
                d = fmaf(a.z, c.z, d);
                d = fmaf(a.w, c.w, d);
            }
            float var = vR[ii] + vC[cur][jj] + d * (2.f / 64.f);
            inv[tid] = rsqrtf(var + LN_EPS);
        }
        __syncthreads();

        // phase B: streaming stores, gamma folded in
        const float* invg = inv + rw * 16;
        float4* op = (float4*)out +
                     ((size_t)(b * N_ + i0 + rw) * N_ + (jg * JT + t) * 16) * 16 + f4;
#pragma unroll
        for (int jj = 0; jj < 16; jj++) {
            float4 c = ((const float4*)(csc + jj * PADR))[f4];
            float iv = invg[jj];
            float4 o;
            o.x = fmaf(fmaf(c.x, gm.x, u.x), iv, bt.x);
            o.y = fmaf(fmaf(c.y, gm.y, u.y), iv, bt.y);
            o.z = fmaf(fmaf(c.z, gm.z, u.z), iv, bt.z);
            o.w = fmaf(fmaf(c.w, gm.w, u.w), iv, bt.w);
            __stcs(op + (size_t)jj * 16, o);
        }

        // commit prefetch to the other buffer
        if (t + 1 < JT) {
            ((float4*)(cs[nxt] + rw * PADR))[f4] = pc;
            if (tid < 16) vC[nxt][tid] = pv;
        }
        __syncthreads();
    }
}

// ---------------- launch -------------------------------------------------------
#define KB1_SMEM ((1040 + 8192 + 8192) * 4)

extern "C" void kernel_launch(void* const* d_in, const int* in_sizes, int n_in,
                              void* d_out, int out_size) {
    const float* x     = (const float*)d_in[0];  // [2,768,512]
    const float* Wr    = (const float*)d_in[1];  // [64,512]
    const float* Wc    = (const float*)d_in[2];  // [64,512]
    const float* We    = (const float*)d_in[3];  // [64,64]
    const float* gamma = (const float*)d_in[4];  // [64]
    const float* beta  = (const float*)d_in[5];  // [64]
    float* out = (float*)d_out;                  // [2,768,768,64] fp32

    static int smem_set = 0;
    if (!smem_set) {
        cudaFuncSetAttribute(kB1, cudaFuncAttributeMaxDynamicSharedMemorySize, KB1_SMEM);
        smem_set = 1;
    }

    kT<<<dim3(16, 2, 2), 256>>>(Wr, Wc);
    kB1<<<192, 256, KB1_SMEM>>>(x);
    kB2<<<BN_ / 4, 256>>>(We);
    kC<<<dim3(N_ / 16, B_, N_ / 16 / JT), 256>>>(gamma, beta, out);
}

// round 9
// speedup vs baseline: 1.1080x; 1.0274x over previous
#include <cuda_runtime.h>
#include <cstddef>
#include <cstdint>

#define B_   2
#define N_   768
#define BN_  1536
#define D_   512
#define E_   64
#define LN_EPS 1e-5f
#define PADR 68            // kC smem row pitch (floats)
#define XP   130           // kB x-tile pitch (floats)
#define WP   66            // kB weight-tile pitch (floats, even for 8B-aligned ull)
#define JT   8             // kC j-tiles per block

typedef unsigned long long ull;

// ---------------- scratch ----------------
__device__ float g_Rc[BN_ * E_];    // centered R'
__device__ float g_Cc[BN_ * E_];    // centered C'
__device__ float g_varR[BN_];
__device__ float g_varC[BN_];

// -------- f32x2 helpers --------
__device__ __forceinline__ void ffma2(ull& d, ull a, ull b) {
    asm("fma.rn.f32x2 %0, %1, %2, %0;" : "+l"(d) : "l"(a), "l"(b));
}
__device__ __forceinline__ ull pack2(float x) {
    ull r; unsigned u = __float_as_uint(x);
    asm("mov.b64 %0, {%1, %1};" : "=l"(r) : "r"(u));
    return r;
}

// ---------------- kernel B: the entire prologue, fused ------------------------
// grid 96, block 256, 16 rows/block.
// 1) transpose raw Wr/Wc chunks into smem (float2-paired, ~conflict-free)
// 2) f32x2 GEMM -> raw T rows (all 64 f in-block)
// 3) apply W_edges in-block, stats, centering -> g_Rc/g_Cc/g_var*
// smem floats: xs 2080 | wrs 8448 | wcs 8448 | wes 4160 | Trw 2048 | Tcw 2048
// P (16384) aliases wrs+wcs (16896) after GEMM.
extern __shared__ float sm_b[];
__global__ void __launch_bounds__(256) kB(const float* __restrict__ x,
                                          const float* __restrict__ Wr,
                                          const float* __restrict__ Wc,
                                          const float* __restrict__ We) {
    float* xs  = sm_b;                 // 2080
    float* wrs = sm_b + 2080;          // 8448
    float* wcs = wrs + 8448;           // 8448
    float* wes = wcs + 8448;           // 4160 (pitch 65)
    float* Trw = wes + 4160;           // 2048
    float* Tcw = Trw + 2048;           // 2048
    float* P   = sm_b + 2080;          // alias 16384 <= 16896

    int tid  = threadIdx.x;
    int f2   = tid & 31;
    int w    = tid >> 5;
    int row0 = blockIdx.x * 16;

    // We transposed: wes[e*65+f] = We[f][e]  (coalesced LDG, conflict-free STS)
    for (int idx = tid; idx < 4096; idx += 256) {
        int f = idx >> 6, e = idx & 63;
        wes[e * 65 + f] = We[f * E_ + e];
    }

    ull aR[16], aC[16];
#pragma unroll
    for (int r = 0; r < 16; r++) { aR[r] = 0ULL; aC[r] = 0ULL; }

    for (int c = 0; c < 4; c++) {
        int d0 = c * 128;
        // transpose weight chunk: thread = (f-pair fp, dd); LDG coalesced along dd,
        // STS.64 at stride 66 floats -> <=2-way conflict
        for (int idx = tid; idx < 4096; idx += 256) {
            int fp = idx >> 7;          // 0..31
            int dd = idx & 127;
            float2 vr, vc;
            vr.x = Wr[(size_t)(2 * fp) * D_ + d0 + dd];
            vr.y = Wr[(size_t)(2 * fp + 1) * D_ + d0 + dd];
            vc.x = Wc[(size_t)(2 * fp) * D_ + d0 + dd];
            vc.y = Wc[(size_t)(2 * fp + 1) * D_ + d0 + dd];
            *(float2*)(wrs + dd * WP + 2 * fp) = vr;
            *(float2*)(wcs + dd * WP + 2 * fp) = vc;
        }
        // x tile: 16 rows x 128 dd
        for (int idx = tid; idx < 1024; idx += 256) {
            int r = idx >> 6, dd2 = idx & 63;
            *(float2*)(xs + r * XP + dd2 * 2) =
                *(const float2*)(x + (size_t)(row0 + r) * D_ + d0 + dd2 * 2);
        }
        __syncthreads();

        int wbase = w * 16;
#pragma unroll
        for (int p = 0; p < 8; p++) {
            int dd = wbase + p * 2;
            ull wr0 = *(const ull*)(wrs + dd * WP + 2 * f2);
            ull wr1 = *(const ull*)(wrs + (dd + 1) * WP + 2 * f2);
            ull wc0 = *(const ull*)(wcs + dd * WP + 2 * f2);
            ull wc1 = *(const ull*)(wcs + (dd + 1) * WP + 2 * f2);
#pragma unroll
            for (int r = 0; r < 16; r++) {
                float2 xv = *(const float2*)(xs + r * XP + dd);
                ull x0 = pack2(xv.x);
                ull x1 = pack2(xv.y);
                ffma2(aR[r], x0, wr0);
                ffma2(aR[r], x1, wr1);
                ffma2(aC[r], x0, wc0);
                ffma2(aC[r], x1, wc1);
            }
        }
        __syncthreads();
    }

    // per-warp partials into P (aliases weight buffers; GEMM done)
#pragma unroll
    for (int r = 0; r < 16; r++) {
        *(ull*)(P + ((w * 2 + 0) * 16 + r) * E_ + 2 * f2) = aR[r];
        *(ull*)(P + ((w * 2 + 1) * 16 + r) * E_ + 2 * f2) = aC[r];
    }
    __syncthreads();

    // reduce 8 warp-partials -> raw T rows in smem
    {
        int row = tid >> 4;
        int fq  = tid & 15;
        float4 R4 = make_float4(0.f, 0.f, 0.f, 0.f);
        float4 C4 = make_float4(0.f, 0.f, 0.f, 0.f);
#pragma unroll
        for (int ww = 0; ww < 8; ww++) {
            float4 pr = *(const float4*)(P + ((ww * 2 + 0) * 16 + row) * E_ + fq * 4);
            float4 pc = *(const float4*)(P + ((ww * 2 + 1) * 16 + row) * E_ + fq * 4);
            R4.x += pr.x; R4.y += pr.y; R4.z += pr.z; R4.w += pr.w;
            C4.x += pc.x; C4.y += pc.y; C4.z += pc.z; C4.w += pc.w;
        }
        *(float4*)(Trw + row * E_ + fq * 4) = R4;
        *(float4*)(Tcw + row * E_ + fq * 4) = C4;
    }
    __syncthreads();

    // edge apply: warp w2 -> rows 2w2, 2w2+1; lane l -> f = l and l+32
    int l  = tid & 31;
    int r0 = 2 * w, r1 = 2 * w + 1;
    float aR0l = 0.f, aR0h = 0.f, aR1l = 0.f, aR1h = 0.f;
    float aC0l = 0.f, aC0h = 0.f, aC1l = 0.f, aC1h = 0.f;
#pragma unroll 4
    for (int e = 0; e < E_; e++) {
        float wl = wes[e * 65 + l];
        float wh = wes[e * 65 + l + 32];
        float t0 = Trw[r0 * E_ + e];
        float t1 = Trw[r1 * E_ + e];
        float c0 = Tcw[r0 * E_ + e];
        float c1 = Tcw[r1 * E_ + e];
        aR0l = fmaf(t0, wl, aR0l); aR0h = fmaf(t0, wh, aR0h);
        aR1l = fmaf(t1, wl, aR1l); aR1h = fmaf(t1, wh, aR1h);
        aC0l = fmaf(c0, wl, aC0l); aC0h = fmaf(c0, wh, aC0h);
        aC1l = fmaf(c1, wl, aC1l); aC1h = fmaf(c1, wh, aC1h);
    }

    // stats over the 64 f of each row (within one warp)
    float sR0 = aR0l + aR0h, qR0 = aR0l * aR0l + aR0h * aR0h;
    float sR1 = aR1l + aR1h, qR1 = aR1l * aR1l + aR1h * aR1h;
    float sC0 = aC0l + aC0h, qC0 = aC0l * aC0l + aC0h * aC0h;
    float sC1 = aC1l + aC1h, qC1 = aC1l * aC1l + aC1h * aC1h;
#pragma unroll
    for (int o = 16; o; o >>= 1) {
        sR0 += __shfl_xor_sync(0xffffffffu, sR0, o);
        qR0 += __shfl_xor_sync(0xffffffffu, qR0, o);
        sR1 += __shfl_xor_sync(0xffffffffu, sR1, o);
        qR1 += __shfl_xor_sync(0xffffffffu, qR1, o);
        sC0 += __shfl_xor_sync(0xffffffffu, sC0, o);
        qC0 += __shfl_xor_sync(0xffffffffu, qC0, o);
        sC1 += __shfl_xor_sync(0xffffffffu, sC1, o);
        qC1 += __shfl_xor_sync(0xffffffffu, qC1, o);
    }
    float mR0 = sR0 * (1.f / 64.f), mR1 = sR1 * (1.f / 64.f);
    float mC0 = sC0 * (1.f / 64.f), mC1 = sC1 * (1.f / 64.f);
    int g0 = row0 + r0, g1 = row0 + r1;
    g_Rc[g0 * E_ + l]      = aR0l - mR0;
    g_Rc[g0 * E_ + l + 32] = aR0h - mR0;
    g_Rc[g1 * E_ + l]      = aR1l - mR1;
    g_Rc[g1 * E_ + l + 32] = aR1h - mR1;
    g_Cc[g0 * E_ + l]      = aC0l - mC0;
    g_Cc[g0 * E_ + l + 32] = aC0h - mC0;
    g_Cc[g1 * E_ + l]      = aC1l - mC1;
    g_Cc[g1 * E_ + l + 32] = aC1h - mC1;
    if (l == 0) {
        g_varR[g0] = qR0 * (1.f / 64.f) - mR0 * mR0;
        g_varR[g1] = qR1 * (1.f / 64.f) - mR1 * mR1;
        g_varC[g0] = qC0 * (1.f / 64.f) - mC0 * mC0;
        g_varC[g1] = qC1 * (1.f / 64.f) - mC1 * mC1;
    }
}

// ---------------- kernel C: pipelined multi-j-tile epilogue (unchanged R8) ---
__global__ void __launch_bounds__(256, 4) kC(const float* __restrict__ gamma,
                                             const float* __restrict__ beta,
                                             float* __restrict__ out) {
    __shared__ float rs[16 * PADR];
    __shared__ float cs[2][16 * PADR];
    __shared__ float vR[16];
    __shared__ float vC[2][16];
    __shared__ float inv[256];

    int i0 = blockIdx.x * 16;
    int b  = blockIdx.y;
    int jg = blockIdx.z;
    int tid = threadIdx.x;
    int rowR = b * N_ + i0;
    int rw = tid >> 4;
    int f4 = tid & 15;

    ((float4*)(rs + rw * PADR))[f4] = ((const float4*)(g_Rc + (size_t)(rowR + rw) * E_))[f4];
    if (tid < 16) vR[tid] = g_varR[rowR + tid];
    {
        int rowC = b * N_ + jg * JT * 16;
        ((float4*)(cs[0] + rw * PADR))[f4] = ((const float4*)(g_Cc + (size_t)(rowC + rw) * E_))[f4];
        if (tid < 16) vC[0][tid] = g_varC[rowC + tid];
    }
    __syncthreads();

    float4 gm = __ldg((const float4*)gamma + f4);
    float4 bt = __ldg((const float4*)beta + f4);
    float4 rr = ((const float4*)(rs + rw * PADR))[f4];
    float4 u;
    u.x = rr.x * gm.x; u.y = rr.y * gm.y; u.z = rr.z * gm.z; u.w = rr.w * gm.w;

    for (int t = 0; t < JT; t++) {
        int cur = t & 1, nxt = cur ^ 1;
        float* csc = cs[cur];

        float4 pc;
        float pv = 0.f;
        if (t + 1 < JT) {
            int rowCn = b * N_ + (jg * JT + t + 1) * 16;
            pc = ((const float4*)(g_Cc + (size_t)(rowCn + rw) * E_))[f4];
            if (tid < 16) pv = g_varC[rowCn + tid];
        }

        {
            int ii = tid >> 4, jj = tid & 15;
            const float4* r4 = (const float4*)(rs + ii * PADR);
            const float4* c4 = (const float4*)(csc + jj * PADR);
            float d = 0.f;
#pragma unroll
            for (int k = 0; k < 16; k++) {
                float4 a = r4[k], c = c4[k];
                d = fmaf(a.x, c.x, d);
                d = fmaf(a.y, c.y, d);
                d = fmaf(a.z, c.z, d);
                d = fmaf(a.w, c.w, d);
            }
            float var = vR[ii] + vC[cur][jj] + d * (2.f / 64.f);
            inv[tid] = rsqrtf(var + LN_EPS);
        }
        __syncthreads();

        const float* invg = inv + rw * 16;
        float4* op = (float4*)out +
                     ((size_t)(b * N_ + i0 + rw) * N_ + (jg * JT + t) * 16) * 16 + f4;
#pragma unroll
        for (int jj = 0; jj < 16; jj++) {
            float4 c = ((const float4*)(csc + jj * PADR))[f4];
            float iv = invg[jj];
            float4 o;
            o.x = fmaf(fmaf(c.x, gm.x, u.x), iv, bt.x);
            o.y = fmaf(fmaf(c.y, gm.y, u.y), iv, bt.y);
            o.z = fmaf(fmaf(c.z, gm.z, u.z), iv, bt.z);
            o.w = fmaf(fmaf(c.w, gm.w, u.w), iv, bt.w);
            __stcs(op + (size_t)jj * 16, o);
        }

        if (t + 1 < JT) {
            ((float4*)(cs[nxt] + rw * PADR))[f4] = pc;
            if (tid < 16) vC[nxt][tid] = pv;
        }
        __syncthreads();
    }
}

// ---------------- launch -------------------------------------------------------
#define KB_SMEM ((2080 + 8448 + 8448 + 4160 + 2048 + 2048) * 4)

extern "C" void kernel_launch(void* const* d_in, const int* in_sizes, int n_in,
                              void* d_out, int out_size) {
    const float* x     = (const float*)d_in[0];  // [2,768,512]
    const float* Wr    = (const float*)d_in[1];  // [64,512]
    const float* Wc    = (const float*)d_in[2];  // [64,512]
    const float* We    = (const float*)d_in[3];  // [64,64]
    const float* gamma = (const float*)d_in[4];  // [64]
    const float* beta  = (const float*)d_in[5];  // [64]
    float* out = (float*)d_out;                  // [2,768,768,64] fp32

    static int smem_set = 0;
    if (!smem_set) {
        cudaFuncSetAttribute(kB, cudaFuncAttributeMaxDynamicSharedMemorySize, KB_SMEM);
        smem_set = 1;
    }

    kB<<<96, 256, KB_SMEM>>>(x, Wr, Wc, We);
    kC<<<dim3(N_ / 16, B_, N_ / 16 / JT), 256>>>(gamma, beta, out);
}